// round 10
// baseline (speedup 1.0000x reference)
#include <cuda_runtime.h>
#include <cstdint>

#define TT   256   // timesteps
#define BB   512   // batch
#define NCTA 86    // CTAs = 43 clusters of 2; 43*12 = 516 >= 512 rows

typedef unsigned long long u64;

// Weight layout (per matrix), ulonglong2 index:
//   idx = (m*2 + qp)*512 + j*2 + ks    m in [0,64), qp in {0,1}, j in [0,256), ks in {0,1}
// float f of that ull2:  q = 2*qp + (f>>1),  k = ks*128 + 2*m + (f&1)
//   => .x = packed (Wq0[k0], Wq0[k1]), .y = packed (Wq1[k0], Wq1[k1]), k0=ks*128+2m
// Padded +1024 ull2 for prefetch overshoot.
__device__ ulonglong2 g_W1u [65536 + 1024];  // from W_hh1
__device__ ulonglong2 g_W2au[65536 + 1024];  // from W_ih2
__device__ ulonglong2 g_W2bu[65536 + 1024];  // from W_hh2

__global__ void prep_kernel(const float* __restrict__ Whh1,
                            const float* __restrict__ Wih2,
                            const float* __restrict__ Whh2) {
    int e = blockIdx.x * blockDim.x + threadIdx.x;
    if (e >= 256 * 256 * 4) return;
    int f    = e & 3;
    int idx  = e >> 2;
    int ks   = idx & 1;
    int j    = (idx >> 1) & 255;
    int qp   = (idx >> 9) & 1;
    int m    = idx >> 10;
    int q    = 2 * qp + (f >> 1);
    int k    = ks * 128 + 2 * m + (f & 1);
    int src  = (q * 256 + j) * 256 + k;
    reinterpret_cast<float*>(g_W1u)[e]  = Whh1[src];
    reinterpret_cast<float*>(g_W2au)[e] = Wih2[src];
    reinterpret_cast<float*>(g_W2bu)[e] = Whh2[src];
}

// ---- f32x2 packed helpers ----
__device__ __forceinline__ u64 pack2(float lo, float hi) {
    u64 r;
    asm("mov.b64 %0, {%1, %2};" : "=l"(r) : "f"(lo), "f"(hi));
    return r;
}
__device__ __forceinline__ void unpack2(u64 v, float& lo, float& hi) {
    asm("mov.b64 {%0, %1}, %2;" : "=f"(lo), "=f"(hi) : "l"(v));
}
__device__ __forceinline__ u64 ffma2(u64 a, u64 b, u64 c) {
    u64 d;
    asm("fma.rn.f32x2 %0, %1, %2, %3;" : "=l"(d) : "l"(a), "l"(b), "l"(c));
    return d;
}
__device__ __forceinline__ float hsum(u64 v) {
    float lo, hi;
    unpack2(v, lo, hi);
    return lo + hi;
}
__device__ __forceinline__ float sigmf(float x) {
    return __fdividef(1.0f, 1.0f + __expf(-x));
}
__device__ __forceinline__ float tanhf_fast(float x) {
    return __fdividef(2.0f, 1.0f + __expf(-2.0f * x)) - 1.0f;
}

// ---- cluster helpers ----
__device__ __forceinline__ uint32_t smem_u32(const void* p) {
    return (uint32_t)__cvta_generic_to_shared(p);
}
__device__ __forceinline__ uint32_t mapa_u32(uint32_t addr, uint32_t rank) {
    uint32_t r;
    asm("mapa.shared::cluster.u32 %0, %1, %2;" : "=r"(r) : "r"(addr), "r"(rank));
    return r;
}
__device__ __forceinline__ void sts_peer(uint32_t addr, float v) {
    asm volatile("st.shared::cluster.f32 [%0], %1;" :: "r"(addr), "f"(v) : "memory");
}
#define CLUSTER_SYNC() do { \
    asm volatile("barrier.cluster.arrive.aligned;" ::: "memory"); \
    asm volatile("barrier.cluster.wait.aligned;"   ::: "memory"); } while (0)

// h layout (one buffer): float h[2(ks)][64(m)][12(r)][2(par)], 3072 floats.
// k = ks*128 + 2m + par. One m-step reads 96B = 6 LDS.128 (broadcast).
#define HADDRF(k, r) (((k) >> 7) * 1536 + (((k) & 127) >> 1) * 24 + ((r) * 2) + ((k) & 1))

// one m-step of one matrix, 12 rows: 6 LDS.128 + 24 ffma2
__device__ __forceinline__ void mv12(ulonglong2 w, const float* __restrict__ hb,
                                     int m, u64* __restrict__ a0,
                                     u64* __restrict__ a1) {
    const ulonglong2* hp = reinterpret_cast<const ulonglong2*>(hb + m * 24);
    ulonglong2 H0 = hp[0], H1 = hp[1], H2 = hp[2];
    ulonglong2 H3 = hp[3], H4 = hp[4], H5 = hp[5];
    a0[0]  = ffma2(w.x, H0.x, a0[0]);
    a0[1]  = ffma2(w.x, H0.y, a0[1]);
    a0[2]  = ffma2(w.x, H1.x, a0[2]);
    a0[3]  = ffma2(w.x, H1.y, a0[3]);
    a0[4]  = ffma2(w.x, H2.x, a0[4]);
    a0[5]  = ffma2(w.x, H2.y, a0[5]);
    a0[6]  = ffma2(w.x, H3.x, a0[6]);
    a0[7]  = ffma2(w.x, H3.y, a0[7]);
    a0[8]  = ffma2(w.x, H4.x, a0[8]);
    a0[9]  = ffma2(w.x, H4.y, a0[9]);
    a0[10] = ffma2(w.x, H5.x, a0[10]);
    a0[11] = ffma2(w.x, H5.y, a0[11]);
    a1[0]  = ffma2(w.y, H0.x, a1[0]);
    a1[1]  = ffma2(w.y, H0.y, a1[1]);
    a1[2]  = ffma2(w.y, H1.x, a1[2]);
    a1[3]  = ffma2(w.y, H1.y, a1[3]);
    a1[4]  = ffma2(w.y, H2.x, a1[4]);
    a1[5]  = ffma2(w.y, H2.y, a1[5]);
    a1[6]  = ffma2(w.y, H3.x, a1[6]);
    a1[7]  = ffma2(w.y, H3.y, a1[7]);
    a1[8]  = ffma2(w.y, H4.x, a1[8]);
    a1[9]  = ffma2(w.y, H4.y, a1[9]);
    a1[10] = ffma2(w.y, H5.x, a1[10]);
    a1[11] = ffma2(w.y, H5.y, a1[11]);
}

__global__ void __launch_bounds__(512) __cluster_dims__(2, 1, 1)
lstm_kernel(
    const float* __restrict__ x_in,   // (512,256,2)
    const float* __restrict__ W_ih1,  // (1024,2)
    const float* __restrict__ b_ih1, const float* __restrict__ b_hh1,
    const float* __restrict__ b_ih2, const float* __restrict__ b_hh2,
    const float* __restrict__ W_lin,  // (2,256)
    const float* __restrict__ b_lin,  // (2,)
    float* __restrict__ out)          // (512,256,2)
{
    __shared__ __align__(16) float sh1f[2 * 3072];   // double-buffered h1 (full mirror)
    __shared__ __align__(16) float sh2f[2 * 3072];   // double-buffered h2
    __shared__ __align__(16) u64 exch[128 * 12];     // (jl, r) -> packed (gate_g, gate_o)
    __shared__ float sh_x[2][12][2];
    __shared__ float sh_wl[2][256];

    const int tid  = threadIdx.x;
    const int ks   = tid & 1;            // k-half
    const int jl   = (tid >> 1) & 127;   // local hidden unit
    const int qp   = tid >> 8;           // 0: gates i,f   1: gates g,o
    const int lane = tid & 31;
    const int warp = tid >> 5;

    uint32_t rank;
    asm("mov.u32 %0, %%cluster_ctarank;" : "=r"(rank));
    const int jg     = (int)rank * 128 + jl;    // global hidden unit this CTA owns
    const int brow0  = (blockIdx.x >> 1) * 12;  // cluster's first batch row
    const int rbase  = ks * 6;                  // this thread's 6 of 12 rows

    // per-thread gate constants (gates 2qp, 2qp+1 of unit jg)
    float bias1[2], bias2[2], wx0[2], wx1[2];
#pragma unroll
    for (int g = 0; g < 2; g++) {
        int row = (2 * qp + g) * 256 + jg;
        bias1[g] = b_ih1[row] + b_hh1[row];
        bias2[g] = b_ih2[row] + b_hh2[row];
        wx0[g] = W_ih1[row * 2 + 0];
        wx1[g] = W_ih1[row * 2 + 1];
    }
    if (qp == 0) {
        int idx = jl * 2 + ks;           // covers 0..255
        sh_wl[0][idx] = W_lin[idx];
        sh_wl[1][idx] = W_lin[256 + idx];
    }
    for (int i = tid; i < 2 * 3072; i += 512) { sh1f[i] = 0.0f; sh2f[i] = 0.0f; }
    if (tid < 24) {  // stage x for t=0 into buffer 0
        int r = tid >> 1, c = tid & 1;
        int b = brow0 + r;
        sh_x[0][r][c] = (b < BB) ? x_in[(b * TT + 0) * 2 + c] : 0.0f;
    }

    float c1[6], c2[6];
#pragma unroll
    for (int i = 0; i < 6; i++) { c1[i] = 0.0f; c2[i] = 0.0f; }

    const float blin0 = b_lin[0], blin1 = b_lin[1];
    const int woff = qp * 512 + jg * 2 + ks;
    // peer SMEM base addresses (u32 shared-window)
    const uint32_t p1 = mapa_u32(smem_u32(sh1f), rank ^ 1);
    const uint32_t p2 = mapa_u32(smem_u32(sh2f), rank ^ 1);
    // h write offset (floats) for unit jg, row 0 (add r*2, + buf*3072)
    const int hoff = ((jg >> 7) * 1536) + (((jg & 127) >> 1) * 24) + (jg & 1);

    CLUSTER_SYNC();  // both CTAs zero-initialized before any peer writes

    // prefetch first layer-1 weight
    const ulonglong2* wp = g_W1u + woff;
    ulonglong2 w0 = __ldg(wp);
    wp += 1024;

    for (int t = 0; t < TT; t++) {
        const int bufp = t & 1;        // buffer written this step
        const int bufr = bufp ^ 1;     // buffer holding prev-step h

        u64 A0[12], A1[12];
#pragma unroll
        for (int r = 0; r < 12; r++) { A0[r] = 0ULL; A1[r] = 0ULL; }

        // ===== layer 1 matvec: h1_prev * Whh1^T (j-slice) =====
        {
            const float* h1r = sh1f + bufr * 3072 + ks * 1536;
#pragma unroll 4
            for (int m = 0; m < 64; m++) {
                ulonglong2 wn = __ldg(wp);
                wp += 1024;
                mv12(w0, h1r, m, A0, A1);
                w0 = wn;
            }
        }

        // epilogue 1: cross-ks reduce, + bias + x-term for my 6 rows
        float f0[12], f1[12];
#pragma unroll
        for (int r = 0; r < 12; r++) {
            float t0 = hsum(A0[r]);
            float t1 = hsum(A1[r]);
            f0[r] = t0 + __shfl_xor_sync(0xffffffffu, t0, 1);
            f1[r] = t1 + __shfl_xor_sync(0xffffffffu, t1, 1);
        }
        float g0[6], g1[6];
        {
            const float (*xb)[2] = sh_x[t & 1];
#pragma unroll
            for (int i = 0; i < 6; i++) {
                int r = rbase + i;
                float x0 = xb[r][0], x1 = xb[r][1];
                g0[i] = f0[r] + fmaf(x1, wx1[0], fmaf(x0, wx0[0], bias1[0]));
                g1[i] = f1[r] + fmaf(x1, wx1[1], fmaf(x0, wx0[1], bias1[1]));
            }
        }
        if (qp == 1) {
#pragma unroll
            for (int i = 0; i < 6; i++)
                exch[jl * 12 + rbase + i] = pack2(g0[i], g1[i]);
        }

        // prefetch layer-2 weight heads (hidden under barrier + cell1)
        const ulonglong2* wpa = g_W2au + woff;
        const ulonglong2* wpb = g_W2bu + woff;
        ulonglong2 wa = __ldg(wpa);
        ulonglong2 wb = __ldg(wpb);
        wpa += 1024; wpb += 1024;

        __syncthreads();  // (B) exch visible within CTA

        if (qp == 0) {    // cell 1 for my 6 rows; mirror h1 to local + peer
            int base = bufp * 3072 + hoff;
#pragma unroll
            for (int i = 0; i < 6; i++) {
                int r = rbase + i;
                float gg, go;
                unpack2(exch[jl * 12 + r], gg, go);
                c1[i] = sigmf(g1[i]) * c1[i] + sigmf(g0[i]) * tanhf_fast(gg);
                float h = sigmf(go) * tanhf_fast(c1[i]);
                int off = base + r * 2;
                sh1f[off] = h;
                sts_peer(p1 + (uint32_t)off * 4u, h);
            }
        } else if (tid - 256 < 24 && t + 1 < TT) {
            int idx = tid - 256;
            int r = idx >> 1, c = idx & 1;
            int b = brow0 + r;
            sh_x[(t + 1) & 1][r][c] = (b < BB) ? x_in[(b * TT + t + 1) * 2 + c] : 0.0f;
        }

        CLUSTER_SYNC();   // (C') h1_new complete in both CTAs' mirrors

#pragma unroll
        for (int r = 0; r < 12; r++) { A0[r] = 0ULL; A1[r] = 0ULL; }

        // ===== layer 2 matvec: h1_new * Wih2^T + h2_prev * Whh2^T =====
        {
            const float* h1n = sh1f + bufp * 3072 + ks * 1536;
            const float* h2r = sh2f + bufr * 3072 + ks * 1536;
#pragma unroll 2
            for (int m = 0; m < 64; m++) {
                ulonglong2 wan = __ldg(wpa);
                ulonglong2 wbn = __ldg(wpb);
                wpa += 1024; wpb += 1024;
                mv12(wa, h1n, m, A0, A1);
                mv12(wb, h2r, m, A0, A1);
                wa = wan; wb = wbn;
            }
        }

        // prefetch next step's layer-1 head (harmless at t=255)
        wp = g_W1u + woff;
        w0 = __ldg(wp);
        wp += 1024;

        // epilogue 2
#pragma unroll
        for (int r = 0; r < 12; r++) {
            float t0 = hsum(A0[r]);
            float t1 = hsum(A1[r]);
            f0[r] = t0 + __shfl_xor_sync(0xffffffffu, t0, 1);
            f1[r] = t1 + __shfl_xor_sync(0xffffffffu, t1, 1);
        }
#pragma unroll
        for (int i = 0; i < 6; i++) {
            int r = rbase + i;
            g0[i] = f0[r] + bias2[0];
            g1[i] = f1[r] + bias2[1];
        }
        if (qp == 1) {
#pragma unroll
            for (int i = 0; i < 6; i++)
                exch[jl * 12 + rbase + i] = pack2(g0[i], g1[i]);
        }
        __syncthreads();  // (D)

        if (qp == 0) {    // cell 2; mirror h2 to local + peer
            int base = bufp * 3072 + hoff;
#pragma unroll
            for (int i = 0; i < 6; i++) {
                int r = rbase + i;
                float gg, go;
                unpack2(exch[jl * 12 + r], gg, go);
                c2[i] = sigmf(g1[i]) * c2[i] + sigmf(g0[i]) * tanhf_fast(gg);
                float h = sigmf(go) * tanhf_fast(c2[i]);
                int off = base + r * 2;
                sh2f[off] = h;
                sts_peer(p2 + (uint32_t)off * 4u, h);
            }
        }

        CLUSTER_SYNC();   // (E') h2_new complete in both mirrors

        // ===== y = h2 * W_lin^T + b_lin : warp w -> cluster row rank*6+w =====
        if (warp < 6) {
            int r = (int)rank * 6 + warp;      // cluster-local row
            int b = brow0 + r;
            if (b < BB) {
                const float* h2n = sh2f + bufp * 3072;
                float v0 = 0.0f, v1 = 0.0f;
#pragma unroll
                for (int mm = 0; mm < 8; mm++) {
                    int k = lane + mm * 32;
                    float h = h2n[HADDRF(k, r)];
                    v0 = fmaf(sh_wl[0][k], h, v0);
                    v1 = fmaf(sh_wl[1][k], h, v1);
                }
#pragma unroll
                for (int off = 16; off; off >>= 1) {
                    v0 += __shfl_xor_sync(0xffffffffu, v0, off);
                    v1 += __shfl_xor_sync(0xffffffffu, v1, off);
                }
                if (lane == 0) {
                    out[(b * TT + t) * 2 + 0] = v0 + blin0;
                    out[(b * TT + t) * 2 + 1] = v1 + blin1;
                }
            }
        }
        // next step's (C') sync (two cluster syncs back) protects buffer reuse
    }
}

extern "C" void kernel_launch(void* const* d_in, const int* in_sizes, int n_in,
                              void* d_out, int out_size) {
    const float* inputs = (const float*)d_in[0];
    const float* W_ih1  = (const float*)d_in[1];
    const float* W_hh1  = (const float*)d_in[2];
    const float* b_ih1  = (const float*)d_in[3];
    const float* b_hh1  = (const float*)d_in[4];
    const float* W_ih2  = (const float*)d_in[5];
    const float* W_hh2  = (const float*)d_in[6];
    const float* b_ih2  = (const float*)d_in[7];
    const float* b_hh2  = (const float*)d_in[8];
    const float* W_lin  = (const float*)d_in[9];
    const float* b_lin  = (const float*)d_in[10];

    prep_kernel<<<1024, 256>>>(W_hh1, W_ih2, W_hh2);
    lstm_kernel<<<NCTA, 512>>>(inputs, W_ih1, b_ih1, b_hh1, b_ih2, b_hh2,
                               W_lin, b_lin, (float*)d_out);
}

// round 11
// speedup vs baseline: 1.3793x; 1.3793x over previous
#include <cuda_runtime.h>

#define TT   256   // timesteps
#define BB   512   // batch
#define NCTA 86    // CTAs (one per SM; 86*6 >= 512)
#define RR   6     // batch rows per CTA

typedef unsigned long long u64;

// Weight layout (per matrix), ulonglong2 index:
//   idx = m*1024 + qp*512 + j*2 + ks    m in [0,64), qp in {0,1}, j in [0,256), ks in {0,1}
// float f of that ull2:  q = 2*qp + (f>>1),  k = ks*128 + 2*m + (f&1)
//   => .x = packed (Wq0[k0], Wq0[k1]), .y = packed (Wq1[k0], Wq1[k1]), k0 = ks*128+2m
// qp=0 -> gates (i,f); qp=1 -> gates (g,o). Padded +1024 ull2 for prefetch overshoot.
__device__ ulonglong2 g_W1u [65536 + 1024];  // from W_hh1
__device__ ulonglong2 g_W2au[65536 + 1024];  // from W_ih2
__device__ ulonglong2 g_W2bu[65536 + 1024];  // from W_hh2

__global__ void prep_kernel(const float* __restrict__ Whh1,
                            const float* __restrict__ Wih2,
                            const float* __restrict__ Whh2) {
    int e = blockIdx.x * blockDim.x + threadIdx.x;
    if (e >= 256 * 256 * 4) return;
    int f    = e & 3;
    int idx  = e >> 2;
    int ks   = idx & 1;
    int j    = (idx >> 1) & 255;
    int qp   = (idx >> 9) & 1;
    int m    = idx >> 10;
    int q    = 2 * qp + (f >> 1);
    int k    = ks * 128 + 2 * m + (f & 1);
    int src  = (q * 256 + j) * 256 + k;
    reinterpret_cast<float*>(g_W1u)[e]  = Whh1[src];
    reinterpret_cast<float*>(g_W2au)[e] = Wih2[src];
    reinterpret_cast<float*>(g_W2bu)[e] = Whh2[src];
}

// ---- f32x2 packed helpers ----
__device__ __forceinline__ u64 pack2(float lo, float hi) {
    u64 r;
    asm("mov.b64 %0, {%1, %2};" : "=l"(r) : "f"(lo), "f"(hi));
    return r;
}
__device__ __forceinline__ void unpack2(u64 v, float& lo, float& hi) {
    asm("mov.b64 {%0, %1}, %2;" : "=f"(lo), "=f"(hi) : "l"(v));
}
__device__ __forceinline__ u64 ffma2(u64 a, u64 b, u64 c) {
    u64 d;
    asm("fma.rn.f32x2 %0, %1, %2, %3;" : "=l"(d) : "l"(a), "l"(b), "l"(c));
    return d;
}
__device__ __forceinline__ float hsum(u64 v) {
    float lo, hi;
    unpack2(v, lo, hi);
    return lo + hi;
}
__device__ __forceinline__ float sigmf(float x) {
    return __fdividef(1.0f, 1.0f + __expf(-x));
}
__device__ __forceinline__ float tanhf_fast(float x) {
    return __fdividef(2.0f, 1.0f + __expf(-2.0f * x)) - 1.0f;
}

// h smem layout: float h[ks:2][m:64][r:6][par:2] = 3072 floats, k = ks*128 + 2m + par
// u64 view per (ks,m): index r holds (h[r][k0], h[r][k1]) — ffma2-ready.
#define HADDRF(k, r) (((k) >> 7) * 1536 + (((k) & 127) >> 1) * 24 + ((r) * 2) + ((k) & 1))

// one m-iter: 2 preloaded weight ull2 (4 gates x k-pair) + 3 LDS.128 -> 24 ffma2
__device__ __forceinline__ void mv4x6(ulonglong2 wif, ulonglong2 wgo,
                                      const float* __restrict__ hb, int m,
                                      u64 (*__restrict__ acc)[6]) {
    const ulonglong2* hp = reinterpret_cast<const ulonglong2*>(hb + m * 24);
    ulonglong2 Ha = hp[0], Hb = hp[1], Hc = hp[2];
    u64 H0 = Ha.x, H1 = Ha.y, H2 = Hb.x, H3 = Hb.y, H4 = Hc.x, H5 = Hc.y;
    acc[0][0] = ffma2(wif.x, H0, acc[0][0]);
    acc[0][1] = ffma2(wif.x, H1, acc[0][1]);
    acc[0][2] = ffma2(wif.x, H2, acc[0][2]);
    acc[0][3] = ffma2(wif.x, H3, acc[0][3]);
    acc[0][4] = ffma2(wif.x, H4, acc[0][4]);
    acc[0][5] = ffma2(wif.x, H5, acc[0][5]);
    acc[1][0] = ffma2(wif.y, H0, acc[1][0]);
    acc[1][1] = ffma2(wif.y, H1, acc[1][1]);
    acc[1][2] = ffma2(wif.y, H2, acc[1][2]);
    acc[1][3] = ffma2(wif.y, H3, acc[1][3]);
    acc[1][4] = ffma2(wif.y, H4, acc[1][4]);
    acc[1][5] = ffma2(wif.y, H5, acc[1][5]);
    acc[2][0] = ffma2(wgo.x, H0, acc[2][0]);
    acc[2][1] = ffma2(wgo.x, H1, acc[2][1]);
    acc[2][2] = ffma2(wgo.x, H2, acc[2][2]);
    acc[2][3] = ffma2(wgo.x, H3, acc[2][3]);
    acc[2][4] = ffma2(wgo.x, H4, acc[2][4]);
    acc[2][5] = ffma2(wgo.x, H5, acc[2][5]);
    acc[3][0] = ffma2(wgo.y, H0, acc[3][0]);
    acc[3][1] = ffma2(wgo.y, H1, acc[3][1]);
    acc[3][2] = ffma2(wgo.y, H2, acc[3][2]);
    acc[3][3] = ffma2(wgo.y, H3, acc[3][3]);
    acc[3][4] = ffma2(wgo.y, H4, acc[3][4]);
    acc[3][5] = ffma2(wgo.y, H5, acc[3][5]);
}

// one matvec pass (64 m-iters) over one weight matrix, 2-deep weight rotation
__device__ __forceinline__ void mvpass(const ulonglong2* __restrict__ wbase,
                                       const float* __restrict__ hb,
                                       u64 (*__restrict__ acc)[6]) {
    const ulonglong2* wp = wbase;
    ulonglong2 wif = __ldg(wp);
    ulonglong2 wgo = __ldg(wp + 512);
    wp += 1024;
#pragma unroll 4
    for (int m = 0; m < 64; m++) {
        ulonglong2 wif_n = __ldg(wp);
        ulonglong2 wgo_n = __ldg(wp + 512);
        wp += 1024;
        mv4x6(wif, wgo, hb, m, acc);
        wif = wif_n;
        wgo = wgo_n;
    }
}

__global__ void __launch_bounds__(512) lstm_kernel(
    const float* __restrict__ x_in,   // (512,256,2)
    const float* __restrict__ W_ih1,  // (1024,2)
    const float* __restrict__ b_ih1, const float* __restrict__ b_hh1,
    const float* __restrict__ b_ih2, const float* __restrict__ b_hh2,
    const float* __restrict__ W_lin,  // (2,256)
    const float* __restrict__ b_lin,  // (2,)
    float* __restrict__ out)          // (512,256,2)
{
    __shared__ __align__(16) float sh1f[3072];
    __shared__ __align__(16) float sh2f[3072];
    __shared__ float sh_x[2][RR][2];
    __shared__ float sh_wl[2][256];

    const int tid  = threadIdx.x;
    const int ks   = tid & 1;        // k-half this thread accumulates
    const int j    = tid >> 1;       // hidden unit (0..255)
    const int b0   = blockIdx.x * RR;
    const int lane = tid & 31;
    const int warp = tid >> 5;
    const int rb   = ks * 3;         // my 3 batch rows: rb .. rb+2

    // per-thread constants, all 4 gates of unit j
    float bias1[4], bias2[4], wx0[4], wx1[4];
#pragma unroll
    for (int q = 0; q < 4; q++) {
        int row = q * 256 + j;
        bias1[q] = b_ih1[row] + b_hh1[row];
        bias2[q] = b_ih2[row] + b_hh2[row];
        wx0[q] = W_ih1[row * 2 + 0];
        wx1[q] = W_ih1[row * 2 + 1];
    }
    if (tid < 256) {
        sh_wl[0][tid] = W_lin[tid];
        sh_wl[1][tid] = W_lin[256 + tid];
    }
    for (int i = tid; i < 3072; i += 512) { sh1f[i] = 0.0f; sh2f[i] = 0.0f; }
    if (tid < 12) {  // stage x for t=0
        int r = tid >> 1, c = tid & 1;
        int b = b0 + r;
        sh_x[0][r][c] = (b < BB) ? x_in[(b * TT + 0) * 2 + c] : 0.0f;
    }

    float c1[3] = {0.0f, 0.0f, 0.0f};
    float c2[3] = {0.0f, 0.0f, 0.0f};

    const float blin0 = b_lin[0], blin1 = b_lin[1];
    const int   woff  = j * 2 + ks;
    const float* hme1 = sh1f + ks * 1536;   // my k-half of h1
    const float* hme2 = sh2f + ks * 1536;   // my k-half of h2
    const int   hw    = HADDRF(j, 0);       // h write base for unit j (+ r*2)

    __syncthreads();

    for (int t = 0; t < TT; t++) {
        // stage x for t+1 early (read at cell1 of t+1; barriers B..E intervene)
        if (tid < 12 && t + 1 < TT) {
            int r = tid >> 1, c = tid & 1;
            int b = b0 + r;
            sh_x[(t + 1) & 1][r][c] = (b < BB) ? x_in[(b * TT + t + 1) * 2 + c] : 0.0f;
        }

        u64 acc[4][6];
#pragma unroll
        for (int q = 0; q < 4; q++)
#pragma unroll
            for (int r = 0; r < 6; r++) acc[q][r] = 0ULL;

        // ===== layer 1 matvec: h1 * Whh1^T (my k-half) =====
        mvpass(g_W1u + woff, hme1, acc);

        // reduce: k-parity hsum + cross-k-half shfl (partner = lane^1)
        float g[4][6];
#pragma unroll
        for (int q = 0; q < 4; q++)
#pragma unroll
            for (int r = 0; r < 6; r++) {
                float s = hsum(acc[q][r]);
                s += __shfl_xor_sync(0xffffffffu, s, 1);
                g[q][r] = s;
            }

        __syncthreads();  // (B) all sh1 reads done

        // cell 1 for my 3 rows (have all 4 gates locally)
        {
            const float (*xb)[2] = sh_x[t & 1];
#pragma unroll
            for (int i = 0; i < 3; i++) {
                int r = rb + i;
                float x0 = xb[r][0], x1 = xb[r][1];
                float gi = g[0][r] + fmaf(x1, wx1[0], fmaf(x0, wx0[0], bias1[0]));
                float gf = g[1][r] + fmaf(x1, wx1[1], fmaf(x0, wx0[1], bias1[1]));
                float gg = g[2][r] + fmaf(x1, wx1[2], fmaf(x0, wx0[2], bias1[2]));
                float go = g[3][r] + fmaf(x1, wx1[3], fmaf(x0, wx0[3], bias1[3]));
                c1[i] = sigmf(gf) * c1[i] + sigmf(gi) * tanhf_fast(gg);
                sh1f[hw + r * 2] = sigmf(go) * tanhf_fast(c1[i]);
            }
        }
        __syncthreads();  // (C) new h1 visible

#pragma unroll
        for (int q = 0; q < 4; q++)
#pragma unroll
            for (int r = 0; r < 6; r++) acc[q][r] = 0ULL;

        // ===== layer 2: two sequential passes keep weight regs bounded =====
        mvpass(g_W2au + woff, hme1, acc);   // Wih2 * h1_new
        mvpass(g_W2bu + woff, hme2, acc);   // Whh2 * h2_prev

#pragma unroll
        for (int q = 0; q < 4; q++)
#pragma unroll
            for (int r = 0; r < 6; r++) {
                float s = hsum(acc[q][r]);
                s += __shfl_xor_sync(0xffffffffu, s, 1);
                g[q][r] = s;
            }

        __syncthreads();  // (D) all sh2 reads done

        // cell 2 for my 3 rows
#pragma unroll
        for (int i = 0; i < 3; i++) {
            int r = rb + i;
            float gi = g[0][r] + bias2[0];
            float gf = g[1][r] + bias2[1];
            float gg = g[2][r] + bias2[2];
            float go = g[3][r] + bias2[3];
            c2[i] = sigmf(gf) * c2[i] + sigmf(gi) * tanhf_fast(gg);
            sh2f[hw + r * 2] = sigmf(go) * tanhf_fast(c2[i]);
        }
        __syncthreads();  // (E) new h2 visible

        // ===== y = h2 * W_lin^T + b_lin : warp r -> batch row r =====
        if (warp < RR) {
            int r = warp;
            int b = b0 + r;
            if (b < BB) {
                float v0 = 0.0f, v1 = 0.0f;
#pragma unroll
                for (int mm = 0; mm < 8; mm++) {
                    int k = lane + mm * 32;
                    float h = sh2f[HADDRF(k, r)];
                    v0 = fmaf(sh_wl[0][k], h, v0);
                    v1 = fmaf(sh_wl[1][k], h, v1);
                }
#pragma unroll
                for (int off = 16; off; off >>= 1) {
                    v0 += __shfl_xor_sync(0xffffffffu, v0, off);
                    v1 += __shfl_xor_sync(0xffffffffu, v1, off);
                }
                if (lane == 0) {
                    out[(b * TT + t) * 2 + 0] = v0 + blin0;
                    out[(b * TT + t) * 2 + 1] = v1 + blin1;
                }
            }
        }
        // next step's (B) barrier orders sh1 reuse; (D) orders sh2 reuse
    }
}

extern "C" void kernel_launch(void* const* d_in, const int* in_sizes, int n_in,
                              void* d_out, int out_size) {
    const float* inputs = (const float*)d_in[0];
    const float* W_ih1  = (const float*)d_in[1];
    const float* W_hh1  = (const float*)d_in[2];
    const float* b_ih1  = (const float*)d_in[3];
    const float* b_hh1  = (const float*)d_in[4];
    const float* W_ih2  = (const float*)d_in[5];
    const float* W_hh2  = (const float*)d_in[6];
    const float* b_ih2  = (const float*)d_in[7];
    const float* b_hh2  = (const float*)d_in[8];
    const float* W_lin  = (const float*)d_in[9];
    const float* b_lin  = (const float*)d_in[10];

    prep_kernel<<<1024, 256>>>(W_hh1, W_ih2, W_hh2);
    lstm_kernel<<<NCTA, 512>>>(inputs, W_ih1, b_ih1, b_hh1, b_ih2, b_hh2,
                               W_lin, b_lin, (float*)d_out);
}